// round 14
// baseline (speedup 1.0000x reference)
#include <cuda_runtime.h>
#include <cuda_fp16.h>
#include <cstdint>

// ---------------- device scratch (allocations are forbidden) ----------------
__device__ float g_target[64 * 1024];          // input @ W_q^T  (B, D)
__device__ float g_epart[8 * 64 * 1024];       // per-d-tile energy partials (8, B*S)
__device__ __half g_ctx_h[64 * 1024 * 1024];   // fp16 context (128 MB)
__device__ __half g_wpre_h[1024 * 1024];       // fp16 W_pre (2 MB)

// ---------------- helpers ----------------
__device__ __forceinline__ uint32_t smem_u32(const void* p) {
    uint32_t a;
    asm("{ .reg .u64 t; cvta.to.shared.u64 t, %1; cvt.u32.u64 %0, t; }" : "=r"(a) : "l"(p));
    return a;
}
__device__ __forceinline__ void cp_async16(uint32_t dst, const void* src) {
    asm volatile("cp.async.cg.shared.global [%0], [%1], 16;" :: "r"(dst), "l"(src));
}
__device__ __forceinline__ void cp_commit() { asm volatile("cp.async.commit_group;" ::: "memory"); }
template<int N> __device__ __forceinline__ void cp_wait() {
    asm volatile("cp.async.wait_group %0;" :: "n"(N) : "memory");
}
__device__ __forceinline__ float tanh_fast(float x) {
    float y;
    asm("tanh.approx.f32 %0, %1;" : "=f"(y) : "f"(x));
    return y;
}
__device__ __forceinline__ void ldsm4(uint32_t& r0, uint32_t& r1, uint32_t& r2,
                                      uint32_t& r3, uint32_t addr) {
    asm volatile("ldmatrix.sync.aligned.m8n8.x4.shared.b16 {%0,%1,%2,%3}, [%4];"
                 : "=r"(r0), "=r"(r1), "=r"(r2), "=r"(r3) : "r"(addr));
}
__device__ __forceinline__ void mma_f16(float* d, const uint32_t* a, uint32_t b0, uint32_t b1) {
    asm volatile(
        "mma.sync.aligned.m16n8k16.row.col.f32.f16.f16.f32 "
        "{%0,%1,%2,%3}, {%4,%5,%6,%7}, {%8,%9}, {%0,%1,%2,%3};"
        : "+f"(d[0]), "+f"(d[1]), "+f"(d[2]), "+f"(d[3])
        : "r"(a[0]), "r"(a[1]), "r"(a[2]), "r"(a[3]), "r"(b0), "r"(b1));
}
__device__ __forceinline__ void stg_cs_v2(float* p, float v0, float v1) {
    asm volatile("st.global.cs.v2.f32 [%0], {%1, %2};" :: "l"(p), "f"(v0), "f"(v1) : "memory");
}

// =====================================================================
// k01: fused f32->fp16 conversion (blocks >=64) + target GEMM (blocks <64)
//   target[b][d] = sum_a input[b][a] * W_q[d][a]   (fp32 exact)
// =====================================================================
constexpr int K01_CVT_BLOCKS = 4096;
__global__ void k01_cvt_target(
    const float4* __restrict__ ctx, const float4* __restrict__ wpre,
    const float* __restrict__ inp, const float* __restrict__ Wq)
{
    __shared__ float insh[8][1024];
    const int bid = blockIdx.x;
    const int tid = threadIdx.x;

    if (bid < 64) {
        // ---- k1: target GEMM ----
        const int dt = bid >> 3, bg = bid & 7;
        for (int i = tid; i < 8192; i += 256)
            insh[i >> 10][i & 1023] = inp[(bg * 8 + (i >> 10)) * 1024 + (i & 1023)];
        __syncthreads();
        const int w = tid >> 5, l = tid & 31;
        for (int j = 0; j < 16; j++) {
            const int d = dt * 128 + w * 16 + j;
            const float* wr = Wq + (size_t)d * 1024;
            float acc[8] = {0.f, 0.f, 0.f, 0.f, 0.f, 0.f, 0.f, 0.f};
            for (int a = l; a < 1024; a += 32) {
                const float wv = wr[a];
#pragma unroll
                for (int bb = 0; bb < 8; bb++) acc[bb] += wv * insh[bb][a];
            }
#pragma unroll
            for (int bb = 0; bb < 8; bb++) {
                float v = acc[bb];
#pragma unroll
                for (int off = 16; off; off >>= 1) v += __shfl_xor_sync(0xffffffffu, v, off);
                if (l == 0) g_target[(bg * 8 + bb) * 1024 + d] = v;
            }
        }
        return;
    }

    // ---- k0: conversion ----
    const int stride = K01_CVT_BLOCKS * 256;
    const int t0 = (bid - 64) * 256 + tid;
    uint2* dw = reinterpret_cast<uint2*>(g_wpre_h);
    for (int i = t0; i < 262144; i += stride) {
        float4 v = wpre[i];
        __half2 h0 = __float22half2_rn(make_float2(v.x, v.y));
        __half2 h1 = __float22half2_rn(make_float2(v.z, v.w));
        uint2 o;
        o.x = *reinterpret_cast<uint32_t*>(&h0);
        o.y = *reinterpret_cast<uint32_t*>(&h1);
        dw[i] = o;
    }
    uint2* dc = reinterpret_cast<uint2*>(g_ctx_h);
    for (int i = t0; i < 16777216; i += stride) {
        float4 v = ctx[i];
        __half2 h0 = __float22half2_rn(make_float2(v.x, v.y));
        __half2 h1 = __float22half2_rn(make_float2(v.z, v.w));
        uint2 o;
        o.x = *reinterpret_cast<uint32_t*>(&h0);
        o.y = *reinterpret_cast<uint32_t*>(&h1);
        dc[i] = o;
    }
}

// =====================================================================
// k2: fp16 m16n8k16 GEMM + fused tanh/energy epilogue  (round-10 exact
//   mainloop; epilogue uses streaming stores for precompute)
//   CTA 128(M) x 128(N), 256 threads (8 warps as 2m x 4n, warp 64x32).
//   K=1024 in 32 chunks of 32; 4-stage ring, cp_wait<2>, 1 barrier/chunk.
// =====================================================================
constexpr int K2_STAGE   = 16384;
constexpr int K2_VEC_OFF = 65536;   // 4 x 128 floats
constexpr int K2_ESH_OFF = 67584;   // 128 x 4 floats
constexpr int K2_SMEM    = 69632;

struct K2Ctx {
    const __half *gA0, *gA1, *gB0, *gB1;
    uint32_t dA0, dA1, dB0, dB1;
    uint32_t offA0[4], offA1[4], offB0[2], offB1[2];
};

__device__ __forceinline__ void k2_compute(const K2Ctx& c, uint32_t stb,
                                           float (*acc)[4][4]) {
#pragma unroll
    for (int h = 0; h < 2; h++) {
        uint32_t a[4][4], bq[2][4];
#pragma unroll
        for (int tp = 0; tp < 2; tp++)
            ldsm4(bq[tp][0], bq[tp][1], bq[tp][2], bq[tp][3],
                  stb + (h ? c.offB1[tp] : c.offB0[tp]));
#pragma unroll
        for (int tm = 0; tm < 4; tm++)
            ldsm4(a[tm][0], a[tm][1], a[tm][2], a[tm][3],
                  stb + (h ? c.offA1[tm] : c.offA0[tm]));
#pragma unroll
        for (int tm = 0; tm < 4; tm++)
#pragma unroll
            for (int tn = 0; tn < 4; tn++)
                mma_f16(acc[tm][tn], a[tm],
                        bq[tn >> 1][tn & 1], bq[tn >> 1][2 + (tn & 1)]);
    }
}
__device__ __forceinline__ void k2_prefetch(const K2Ctx& c, uint32_t so, int ko) {
    cp_async16(c.dA0 + so, c.gA0 + ko);
    cp_async16(c.dA1 + so, c.gA1 + ko);
    cp_async16(c.dB0 + so, c.gB0 + ko);
    cp_async16(c.dB1 + so, c.gB1 + ko);
    cp_commit();
}

__global__ void __launch_bounds__(256, 2) k2_gemm(
    const float* __restrict__ bpre, const float* __restrict__ cov,
    const float* __restrict__ Wv, const float* __restrict__ Wcov,
    float* __restrict__ outPre)
{
    extern __shared__ char smem[];
    const uint32_t sb = smem_u32(smem);
    float* vecs = (float*)(smem + K2_VEC_OFF);
    float (*e_sh)[4] = (float (*)[4])(smem + K2_ESH_OFF);

    const int nt = blockIdx.x;                 // 0..7   (128-wide d tile)
    const int mt = blockIdx.y;                 // 0..511 (128-row tile)
    const int tid = threadIdx.x;
    const int lane = tid & 31, warp = tid >> 5;
    const int wm = (warp & 1) * 64, wn = (warp >> 1) * 32;
    const int d0 = nt * 128;
    const size_t row0 = (size_t)mt * 128;
    const int b = mt >> 3;

    if (tid < 128) {
        vecs[tid]       = bpre[d0 + tid];
        vecs[128 + tid] = g_target[b * 1024 + d0 + tid];
        vecs[256 + tid] = Wv[d0 + tid];
        vecs[384 + tid] = Wcov[d0 + tid];
    }

    K2Ctx c;
    {
        const int jc = tid & 3;
        const int r0 = tid >> 2;               // 0..63
        c.gA0 = g_ctx_h + (row0 + r0) * 1024 + jc * 8;
        c.gA1 = c.gA0 + 64 * 1024;
        c.gB0 = g_wpre_h + (size_t)(d0 + r0) * 1024 + jc * 8;
        c.gB1 = c.gB0 + 64 * 1024;
        const uint32_t sw0 = (uint32_t)((jc ^ ((r0 >> 1) & 3)) << 4);
        c.dA0 = sb + (uint32_t)(r0 * 64) + sw0;
        c.dA1 = c.dA0 + 4096;
        c.dB0 = c.dA0 + 8192;
        c.dB1 = c.dB0 + 4096;
    }
    {
        const int sub = lane >> 3, idx = lane & 7;
        const int rit = (sub & 1) * 8 + idx;
        const uint32_t kseg = (uint32_t)(sub >> 1);
#pragma unroll
        for (int t = 0; t < 4; t++) {
            const int rA = wm + t * 16 + rit;
            c.offA0[t] = (uint32_t)(rA * 64 + ((kseg ^ ((rA >> 1) & 3)) << 4));
            c.offA1[t] = c.offA0[t] ^ 0x20u;
        }
#pragma unroll
        for (int t = 0; t < 2; t++) {
            const int rB = wn + t * 16 + rit;
            c.offB0[t] = (uint32_t)(8192 + rB * 64 + ((kseg ^ ((rB >> 1) & 3)) << 4));
            c.offB1[t] = c.offB0[t] ^ 0x20u;
        }
    }

    float acc[4][4][4];
#pragma unroll
    for (int i = 0; i < 4; i++)
#pragma unroll
        for (int j = 0; j < 4; j++)
#pragma unroll
            for (int r = 0; r < 4; r++) acc[i][j][r] = 0.f;

    // prologue: chunks 0..2 into stages 0..2
    k2_prefetch(c, 0 * K2_STAGE, 0);
    k2_prefetch(c, 1 * K2_STAGE, 32);
    k2_prefetch(c, 2 * K2_STAGE, 64);

    // main: 7 groups of 4 chunks (0..27), prefetch kt+3 (3..30)
    for (int g4 = 0; g4 < 7; g4++) {
#pragma unroll
        for (int s = 0; s < 4; s++) {
            cp_wait<2>();
            __syncthreads();
            k2_prefetch(c, (uint32_t)(((s + 3) & 3) * K2_STAGE), (s + 3) * 32);
            k2_compute(c, sb + s * K2_STAGE, acc);
        }
        c.gA0 += 128; c.gA1 += 128; c.gB0 += 128; c.gB1 += 128;
    }
    // tail: chunks 28..31 (stages 0..3); prefetch 31 at first iter
    {
        cp_wait<2>(); __syncthreads();
        k2_prefetch(c, 3 * K2_STAGE, 96);      // chunk 31
        k2_compute(c, sb + 0 * K2_STAGE, acc);
        cp_wait<2>(); __syncthreads();
        k2_compute(c, sb + 1 * K2_STAGE, acc);
        cp_wait<1>(); __syncthreads();
        k2_compute(c, sb + 2 * K2_STAGE, acc);
        cp_wait<0>(); __syncthreads();
        k2_compute(c, sb + 3 * K2_STAGE, acc);
    }

    // ---------------- epilogue: bias + precompute (streaming) + tanh/energy ----
    const int g = lane >> 2, t4 = lane & 3;
    const float* bias_sh = vecs;
    const float* tgt_sh  = vecs + 128;
    const float* wv_sh   = vecs + 256;
    const float* wcov_sh = vecs + 384;

#pragma unroll
    for (int tm = 0; tm < 4; tm++) {
#pragma unroll
        for (int h = 0; h < 2; h++) {
            const int rowL = wm + tm * 16 + h * 8 + g;
            const size_t grow = row0 + rowL;
            const float cv = cov[grow];
            float* orow = outPre + grow * 1024 + d0;
            float e = 0.f;
#pragma unroll
            for (int tn = 0; tn < 4; tn++) {
                const int colL = wn + tn * 8 + 2 * t4;
                const float v0 = acc[tm][tn][h * 2 + 0] + bias_sh[colL];
                const float v1 = acc[tm][tn][h * 2 + 1] + bias_sh[colL + 1];
                stg_cs_v2(orow + colL, v0, v1);
                e += tanh_fast(v0 + tgt_sh[colL]     + cv * wcov_sh[colL])     * wv_sh[colL];
                e += tanh_fast(v1 + tgt_sh[colL + 1] + cv * wcov_sh[colL + 1]) * wv_sh[colL + 1];
            }
            e += __shfl_xor_sync(0xffffffffu, e, 1);
            e += __shfl_xor_sync(0xffffffffu, e, 2);
            if (t4 == 0) e_sh[rowL][warp >> 1] = e;
        }
    }
    __syncthreads();
    if (tid < 128)
        g_epart[(size_t)nt * 65536 + row0 + tid] =
            (e_sh[tid][0] + e_sh[tid][1]) + (e_sh[tid][2] + e_sh[tid][3]);
}

// =====================================================================
// k3: energy reduce + softmax + coverage. One block per b, 256 threads.
// =====================================================================
__global__ void k3_softmax(const float* __restrict__ cov, float* __restrict__ out) {
    __shared__ float red[32];
    const int b = blockIdx.x, tid = threadIdx.x;
    float e[4];
#pragma unroll
    for (int i = 0; i < 4; i++) {
        const int s = tid + i * 256;
        float v = 0.f;
#pragma unroll
        for (int nt = 0; nt < 8; nt++) v += g_epart[(size_t)nt * 65536 + b * 1024 + s];
        e[i] = v;
    }
    float mx = fmaxf(fmaxf(e[0], e[1]), fmaxf(e[2], e[3]));
#pragma unroll
    for (int off = 16; off; off >>= 1) mx = fmaxf(mx, __shfl_xor_sync(0xffffffffu, mx, off));
    if ((tid & 31) == 0) red[tid >> 5] = mx;
    __syncthreads();
    if (tid < 32) {
        float m = (tid < 8) ? red[tid] : -1e30f;
#pragma unroll
        for (int off = 4; off; off >>= 1) m = fmaxf(m, __shfl_xor_sync(0xffffffffu, m, off));
        red[tid] = m;
    }
    __syncthreads();
    mx = red[0];
    __syncthreads();

    float ex[4], sum = 0.f;
#pragma unroll
    for (int i = 0; i < 4; i++) { ex[i] = __expf(e[i] - mx); sum += ex[i]; }
#pragma unroll
    for (int off = 16; off; off >>= 1) sum += __shfl_xor_sync(0xffffffffu, sum, off);
    if ((tid & 31) == 0) red[tid >> 5] = sum;
    __syncthreads();
    if (tid < 32) {
        float s = (tid < 8) ? red[tid] : 0.f;
#pragma unroll
        for (int off = 4; off; off >>= 1) s += __shfl_xor_sync(0xffffffffu, s, off);
        red[tid] = s;
    }
    __syncthreads();
    const float inv = 1.f / red[0];
#pragma unroll
    for (int i = 0; i < 4; i++) {
        const int s = tid + i * 256;
        const float sc = ex[i] * inv;
        out[65536 + b * 1024 + s]  = sc;                       // score
        out[131072 + b * 1024 + s] = cov[b * 1024 + s] + sc;   // coverage_new
    }
}

// =====================================================================
// k4: weightedContext[b][a] = sum_s score[b][s] * context_h[b][s][a]
// fp16 context. grid (64 b, 8 chunks of 128 cols), 128 threads, MLP=8.
// =====================================================================
__global__ void __launch_bounds__(128) k4_wctx(
    const float* __restrict__ score, float* __restrict__ out)
{
    __shared__ float sc[1024];
    __shared__ float part[8][16][8];
    const int b = blockIdx.x, chunk = blockIdx.y, tid = threadIdx.x;
    for (int i = tid; i < 1024; i += 128) sc[i] = score[b * 1024 + i];
    __syncthreads();
    const int c16 = tid & 15, ks = tid >> 4;
    const uint4* cp = reinterpret_cast<const uint4*>(g_ctx_h + (size_t)b * 1048576)
                      + chunk * 16 + c16;
    float acc[8];
#pragma unroll
    for (int j = 0; j < 8; j++) acc[j] = 0.f;
    const int s0 = ks * 128;
    for (int s = 0; s < 128; s += 8) {
        uint4 v[8];
#pragma unroll
        for (int u = 0; u < 8; u++) v[u] = cp[(size_t)(s0 + s + u) * 128];
#pragma unroll
        for (int u = 0; u < 8; u++) {
            const float w = sc[s0 + s + u];
            const __half2* h = reinterpret_cast<const __half2*>(&v[u]);
#pragma unroll
            for (int p = 0; p < 4; p++) {
                float2 f = __half22float2(h[p]);
                acc[p * 2 + 0] += w * f.x;
                acc[p * 2 + 1] += w * f.y;
            }
        }
    }
#pragma unroll
    for (int j = 0; j < 8; j++) part[ks][c16][j] = acc[j];
    __syncthreads();
    const int oc = tid >> 3, oj = tid & 7;
    float v = 0.f;
#pragma unroll
    for (int k = 0; k < 8; k++) v += part[k][oc][oj];
    out[b * 1024 + chunk * 128 + oc * 8 + oj] = v;
}

// =====================================================================
extern "C" void kernel_launch(void* const* d_in, const int* in_sizes, int n_in,
                              void* d_out, int out_size) {
    const float* input   = (const float*)d_in[0];
    const float* context = (const float*)d_in[1];
    const float* cov     = (const float*)d_in[2];
    const float* Wpre    = (const float*)d_in[3];
    const float* bpre    = (const float*)d_in[4];
    const float* Wq      = (const float*)d_in[5];
    const float* Wv      = (const float*)d_in[6];
    const float* Wcov    = (const float*)d_in[7];
    float* out = (float*)d_out;
    // layout: weightedContext (65536) | score (65536) | coverage_new (65536)
    //         | precompute (67108864)

    cudaFuncSetAttribute(k2_gemm, cudaFuncAttributeMaxDynamicSharedMemorySize, K2_SMEM);

    k01_cvt_target<<<K01_CVT_BLOCKS + 64, 256>>>(
        (const float4*)context, (const float4*)Wpre, input, Wq);

    dim3 g2(8, 512);
    k2_gemm<<<g2, 256, K2_SMEM>>>(bpre, cov, Wv, Wcov, out + 196608);

    k3_softmax<<<64, 256>>>(cov, out);

    dim3 g4(64, 8);
    k4_wctx<<<g4, 128>>>(out + 65536, out);
}

// round 15
// speedup vs baseline: 1.0944x; 1.0944x over previous
#include <cuda_runtime.h>
#include <cuda_fp16.h>
#include <cstdint>

// ---------------- device scratch (allocations are forbidden) ----------------
__device__ float g_target[64 * 1024];          // input @ W_q^T  (B, D)
__device__ float g_epart[8 * 64 * 1024];       // per-d-tile energy partials (8, B*S)
__device__ __half g_ctx_h[64 * 1024 * 1024];   // fp16 context (128 MB)
__device__ __half g_wpre_h[1024 * 1024];       // fp16 W_pre (2 MB)

// ---------------- helpers ----------------
__device__ __forceinline__ uint32_t smem_u32(const void* p) {
    uint32_t a;
    asm("{ .reg .u64 t; cvta.to.shared.u64 t, %1; cvt.u32.u64 %0, t; }" : "=r"(a) : "l"(p));
    return a;
}
__device__ __forceinline__ void cp_async16(uint32_t dst, const void* src) {
    asm volatile("cp.async.cg.shared.global [%0], [%1], 16;" :: "r"(dst), "l"(src));
}
__device__ __forceinline__ void cp_commit() { asm volatile("cp.async.commit_group;" ::: "memory"); }
template<int N> __device__ __forceinline__ void cp_wait() {
    asm volatile("cp.async.wait_group %0;" :: "n"(N) : "memory");
}
__device__ __forceinline__ float tanh_fast(float x) {
    float y;
    asm("tanh.approx.f32 %0, %1;" : "=f"(y) : "f"(x));
    return y;
}
__device__ __forceinline__ void ldsm4(uint32_t& r0, uint32_t& r1, uint32_t& r2,
                                      uint32_t& r3, uint32_t addr) {
    asm volatile("ldmatrix.sync.aligned.m8n8.x4.shared.b16 {%0,%1,%2,%3}, [%4];"
                 : "=r"(r0), "=r"(r1), "=r"(r2), "=r"(r3) : "r"(addr));
}
__device__ __forceinline__ void mma_f16(float* d, const uint32_t* a, uint32_t b0, uint32_t b1) {
    asm volatile(
        "mma.sync.aligned.m16n8k16.row.col.f32.f16.f16.f32 "
        "{%0,%1,%2,%3}, {%4,%5,%6,%7}, {%8,%9}, {%0,%1,%2,%3};"
        : "+f"(d[0]), "+f"(d[1]), "+f"(d[2]), "+f"(d[3])
        : "r"(a[0]), "r"(a[1]), "r"(a[2]), "r"(a[3]), "r"(b0), "r"(b1));
}
__device__ __forceinline__ uint2 cvt4(float4 v) {
    __half2 h0 = __float22half2_rn(make_float2(v.x, v.y));
    __half2 h1 = __float22half2_rn(make_float2(v.z, v.w));
    uint2 o;
    o.x = *reinterpret_cast<uint32_t*>(&h0);
    o.y = *reinterpret_cast<uint32_t*>(&h1);
    return o;
}

// =====================================================================
// k0: f32 -> fp16 conversion, MLP=4, no smem.
//   blocks 0..4095: context (each thread 16 elems as 4 passes of 4
//   independent coalesced loads).  blocks 4096..4159: W_pre.
// =====================================================================
__global__ void __launch_bounds__(256) k0_cvt(
    const float4* __restrict__ ctx, const float4* __restrict__ wpre)
{
    const int bid = blockIdx.x;
    if (bid < 4096) {
        const int t = bid * 256 + threadIdx.x;          // 0..1048575
        uint2* dst = reinterpret_cast<uint2*>(g_ctx_h);
#pragma unroll
        for (int p = 0; p < 4; p++) {
            float4 v[4];
#pragma unroll
            for (int u = 0; u < 4; u++)
                v[u] = ctx[t + (p * 4 + u) * 1048576];
#pragma unroll
            for (int u = 0; u < 4; u++)
                dst[t + (p * 4 + u) * 1048576] = cvt4(v[u]);
        }
    } else {
        const int t = (bid - 4096) * 256 + threadIdx.x; // 0..16383
        uint2* dst = reinterpret_cast<uint2*>(g_wpre_h);
#pragma unroll
        for (int p = 0; p < 4; p++) {
            float4 v[4];
#pragma unroll
            for (int u = 0; u < 4; u++)
                v[u] = wpre[t + (p * 4 + u) * 16384];
#pragma unroll
            for (int u = 0; u < 4; u++)
                dst[t + (p * 4 + u) * 16384] = cvt4(v[u]);
        }
    }
}

// =====================================================================
// k1: target[b][d] = sum_a input[b][a] * W_q[d][a]   (fp32 exact)
// =====================================================================
__global__ void k1_target(const float* __restrict__ inp, const float* __restrict__ Wq) {
    __shared__ float insh[8][1024];
    const int dt = blockIdx.x, bg = blockIdx.y, tid = threadIdx.x;
    for (int i = tid; i < 8192; i += 256)
        insh[i >> 10][i & 1023] = inp[(bg * 8 + (i >> 10)) * 1024 + (i & 1023)];
    __syncthreads();
    const int w = tid >> 5, l = tid & 31;
    for (int j = 0; j < 16; j++) {
        const int d = dt * 128 + w * 16 + j;
        const float* wr = Wq + (size_t)d * 1024;
        float acc[8] = {0.f, 0.f, 0.f, 0.f, 0.f, 0.f, 0.f, 0.f};
        for (int a = l; a < 1024; a += 32) {
            const float wv = wr[a];
#pragma unroll
            for (int bb = 0; bb < 8; bb++) acc[bb] += wv * insh[bb][a];
        }
#pragma unroll
        for (int bb = 0; bb < 8; bb++) {
            float v = acc[bb];
#pragma unroll
            for (int off = 16; off; off >>= 1) v += __shfl_xor_sync(0xffffffffu, v, off);
            if (l == 0) g_target[(bg * 8 + bb) * 1024 + d] = v;
        }
    }
}

// =====================================================================
// k2: fp16 m16n8k16 GEMM + fused tanh/energy epilogue  (round-10 exact)
//   CTA 128(M) x 128(N), 256 threads (8 warps as 2m x 4n, warp 64x32).
//   K=1024 in 32 chunks of 32; 4-stage ring, cp_wait<2>, 1 barrier/chunk.
// =====================================================================
constexpr int K2_STAGE   = 16384;
constexpr int K2_VEC_OFF = 65536;   // 4 x 128 floats
constexpr int K2_ESH_OFF = 67584;   // 128 x 4 floats
constexpr int K2_SMEM    = 69632;

struct K2Ctx {
    const __half *gA0, *gA1, *gB0, *gB1;
    uint32_t dA0, dA1, dB0, dB1;
    uint32_t offA0[4], offA1[4], offB0[2], offB1[2];
};

__device__ __forceinline__ void k2_compute(const K2Ctx& c, uint32_t stb,
                                           float (*acc)[4][4]) {
#pragma unroll
    for (int h = 0; h < 2; h++) {
        uint32_t a[4][4], bq[2][4];
#pragma unroll
        for (int tp = 0; tp < 2; tp++)
            ldsm4(bq[tp][0], bq[tp][1], bq[tp][2], bq[tp][3],
                  stb + (h ? c.offB1[tp] : c.offB0[tp]));
#pragma unroll
        for (int tm = 0; tm < 4; tm++)
            ldsm4(a[tm][0], a[tm][1], a[tm][2], a[tm][3],
                  stb + (h ? c.offA1[tm] : c.offA0[tm]));
#pragma unroll
        for (int tm = 0; tm < 4; tm++)
#pragma unroll
            for (int tn = 0; tn < 4; tn++)
                mma_f16(acc[tm][tn], a[tm],
                        bq[tn >> 1][tn & 1], bq[tn >> 1][2 + (tn & 1)]);
    }
}
__device__ __forceinline__ void k2_prefetch(const K2Ctx& c, uint32_t so, int ko) {
    cp_async16(c.dA0 + so, c.gA0 + ko);
    cp_async16(c.dA1 + so, c.gA1 + ko);
    cp_async16(c.dB0 + so, c.gB0 + ko);
    cp_async16(c.dB1 + so, c.gB1 + ko);
    cp_commit();
}

__global__ void __launch_bounds__(256, 2) k2_gemm(
    const float* __restrict__ bpre, const float* __restrict__ cov,
    const float* __restrict__ Wv, const float* __restrict__ Wcov,
    float* __restrict__ outPre)
{
    extern __shared__ char smem[];
    const uint32_t sb = smem_u32(smem);
    float* vecs = (float*)(smem + K2_VEC_OFF);
    float (*e_sh)[4] = (float (*)[4])(smem + K2_ESH_OFF);

    const int nt = blockIdx.x;                 // 0..7   (128-wide d tile)
    const int mt = blockIdx.y;                 // 0..511 (128-row tile)
    const int tid = threadIdx.x;
    const int lane = tid & 31, warp = tid >> 5;
    const int wm = (warp & 1) * 64, wn = (warp >> 1) * 32;
    const int d0 = nt * 128;
    const size_t row0 = (size_t)mt * 128;
    const int b = mt >> 3;

    if (tid < 128) {
        vecs[tid]       = bpre[d0 + tid];
        vecs[128 + tid] = g_target[b * 1024 + d0 + tid];
        vecs[256 + tid] = Wv[d0 + tid];
        vecs[384 + tid] = Wcov[d0 + tid];
    }

    K2Ctx c;
    {
        const int jc = tid & 3;
        const int r0 = tid >> 2;               // 0..63
        c.gA0 = g_ctx_h + (row0 + r0) * 1024 + jc * 8;
        c.gA1 = c.gA0 + 64 * 1024;
        c.gB0 = g_wpre_h + (size_t)(d0 + r0) * 1024 + jc * 8;
        c.gB1 = c.gB0 + 64 * 1024;
        const uint32_t sw0 = (uint32_t)((jc ^ ((r0 >> 1) & 3)) << 4);
        c.dA0 = sb + (uint32_t)(r0 * 64) + sw0;
        c.dA1 = c.dA0 + 4096;
        c.dB0 = c.dA0 + 8192;
        c.dB1 = c.dB0 + 4096;
    }
    {
        const int sub = lane >> 3, idx = lane & 7;
        const int rit = (sub & 1) * 8 + idx;
        const uint32_t kseg = (uint32_t)(sub >> 1);
#pragma unroll
        for (int t = 0; t < 4; t++) {
            const int rA = wm + t * 16 + rit;
            c.offA0[t] = (uint32_t)(rA * 64 + ((kseg ^ ((rA >> 1) & 3)) << 4));
            c.offA1[t] = c.offA0[t] ^ 0x20u;
        }
#pragma unroll
        for (int t = 0; t < 2; t++) {
            const int rB = wn + t * 16 + rit;
            c.offB0[t] = (uint32_t)(8192 + rB * 64 + ((kseg ^ ((rB >> 1) & 3)) << 4));
            c.offB1[t] = c.offB0[t] ^ 0x20u;
        }
    }

    float acc[4][4][4];
#pragma unroll
    for (int i = 0; i < 4; i++)
#pragma unroll
        for (int j = 0; j < 4; j++)
#pragma unroll
            for (int r = 0; r < 4; r++) acc[i][j][r] = 0.f;

    // prologue: chunks 0..2 into stages 0..2
    k2_prefetch(c, 0 * K2_STAGE, 0);
    k2_prefetch(c, 1 * K2_STAGE, 32);
    k2_prefetch(c, 2 * K2_STAGE, 64);

    // main: 7 groups of 4 chunks (0..27), prefetch kt+3 (3..30)
    for (int g4 = 0; g4 < 7; g4++) {
#pragma unroll
        for (int s = 0; s < 4; s++) {
            cp_wait<2>();
            __syncthreads();
            k2_prefetch(c, (uint32_t)(((s + 3) & 3) * K2_STAGE), (s + 3) * 32);
            k2_compute(c, sb + s * K2_STAGE, acc);
        }
        c.gA0 += 128; c.gA1 += 128; c.gB0 += 128; c.gB1 += 128;
    }
    // tail: chunks 28..31 (stages 0..3); prefetch 31 at first iter
    {
        cp_wait<2>(); __syncthreads();
        k2_prefetch(c, 3 * K2_STAGE, 96);      // chunk 31
        k2_compute(c, sb + 0 * K2_STAGE, acc);
        cp_wait<2>(); __syncthreads();
        k2_compute(c, sb + 1 * K2_STAGE, acc);
        cp_wait<1>(); __syncthreads();
        k2_compute(c, sb + 2 * K2_STAGE, acc);
        cp_wait<0>(); __syncthreads();
        k2_compute(c, sb + 3 * K2_STAGE, acc);
    }

    // ---------------- epilogue: bias + precompute + tanh/energy ----------------
    const int g = lane >> 2, t4 = lane & 3;
    const float* bias_sh = vecs;
    const float* tgt_sh  = vecs + 128;
    const float* wv_sh   = vecs + 256;
    const float* wcov_sh = vecs + 384;

#pragma unroll
    for (int tm = 0; tm < 4; tm++) {
#pragma unroll
        for (int h = 0; h < 2; h++) {
            const int rowL = wm + tm * 16 + h * 8 + g;
            const size_t grow = row0 + rowL;
            const float cv = cov[grow];
            float* orow = outPre + grow * 1024 + d0;
            float e = 0.f;
#pragma unroll
            for (int tn = 0; tn < 4; tn++) {
                const int colL = wn + tn * 8 + 2 * t4;
                const float v0 = acc[tm][tn][h * 2 + 0] + bias_sh[colL];
                const float v1 = acc[tm][tn][h * 2 + 1] + bias_sh[colL + 1];
                *reinterpret_cast<float2*>(orow + colL) = make_float2(v0, v1);
                e += tanh_fast(v0 + tgt_sh[colL]     + cv * wcov_sh[colL])     * wv_sh[colL];
                e += tanh_fast(v1 + tgt_sh[colL + 1] + cv * wcov_sh[colL + 1]) * wv_sh[colL + 1];
            }
            e += __shfl_xor_sync(0xffffffffu, e, 1);
            e += __shfl_xor_sync(0xffffffffu, e, 2);
            if (t4 == 0) e_sh[rowL][warp >> 1] = e;
        }
    }
    __syncthreads();
    if (tid < 128)
        g_epart[(size_t)nt * 65536 + row0 + tid] =
            (e_sh[tid][0] + e_sh[tid][1]) + (e_sh[tid][2] + e_sh[tid][3]);
}

// =====================================================================
// k3: energy reduce + softmax + coverage. One block per b, 256 threads.
// =====================================================================
__global__ void k3_softmax(const float* __restrict__ cov, float* __restrict__ out) {
    __shared__ float red[32];
    const int b = blockIdx.x, tid = threadIdx.x;
    float e[4];
#pragma unroll
    for (int i = 0; i < 4; i++) {
        const int s = tid + i * 256;
        float v = 0.f;
#pragma unroll
        for (int nt = 0; nt < 8; nt++) v += g_epart[(size_t)nt * 65536 + b * 1024 + s];
        e[i] = v;
    }
    float mx = fmaxf(fmaxf(e[0], e[1]), fmaxf(e[2], e[3]));
#pragma unroll
    for (int off = 16; off; off >>= 1) mx = fmaxf(mx, __shfl_xor_sync(0xffffffffu, mx, off));
    if ((tid & 31) == 0) red[tid >> 5] = mx;
    __syncthreads();
    if (tid < 32) {
        float m = (tid < 8) ? red[tid] : -1e30f;
#pragma unroll
        for (int off = 4; off; off >>= 1) m = fmaxf(m, __shfl_xor_sync(0xffffffffu, m, off));
        red[tid] = m;
    }
    __syncthreads();
    mx = red[0];
    __syncthreads();

    float ex[4], sum = 0.f;
#pragma unroll
    for (int i = 0; i < 4; i++) { ex[i] = __expf(e[i] - mx); sum += ex[i]; }
#pragma unroll
    for (int off = 16; off; off >>= 1) sum += __shfl_xor_sync(0xffffffffu, sum, off);
    if ((tid & 31) == 0) red[tid >> 5] = sum;
    __syncthreads();
    if (tid < 32) {
        float s = (tid < 8) ? red[tid] : 0.f;
#pragma unroll
        for (int off = 4; off; off >>= 1) s += __shfl_xor_sync(0xffffffffu, s, off);
        red[tid] = s;
    }
    __syncthreads();
    const float inv = 1.f / red[0];
#pragma unroll
    for (int i = 0; i < 4; i++) {
        const int s = tid + i * 256;
        const float sc = ex[i] * inv;
        out[65536 + b * 1024 + s]  = sc;                       // score
        out[131072 + b * 1024 + s] = cov[b * 1024 + s] + sc;   // coverage_new
    }
}

// =====================================================================
// k4: weightedContext[b][a] = sum_s score[b][s] * context_h[b][s][a]
// fp16 context. grid (64 b, 8 chunks of 128 cols), 128 threads, MLP=8.
// =====================================================================
__global__ void __launch_bounds__(128) k4_wctx(
    const float* __restrict__ score, float* __restrict__ out)
{
    __shared__ float sc[1024];
    __shared__ float part[8][16][8];
    const int b = blockIdx.x, chunk = blockIdx.y, tid = threadIdx.x;
    for (int i = tid; i < 1024; i += 128) sc[i] = score[b * 1024 + i];
    __syncthreads();
    const int c16 = tid & 15, ks = tid >> 4;
    const uint4* cp = reinterpret_cast<const uint4*>(g_ctx_h + (size_t)b * 1048576)
                      + chunk * 16 + c16;
    float acc[8];
#pragma unroll
    for (int j = 0; j < 8; j++) acc[j] = 0.f;
    const int s0 = ks * 128;
    for (int s = 0; s < 128; s += 8) {
        uint4 v[8];
#pragma unroll
        for (int u = 0; u < 8; u++) v[u] = cp[(size_t)(s0 + s + u) * 128];
#pragma unroll
        for (int u = 0; u < 8; u++) {
            const float w = sc[s0 + s + u];
            const __half2* h = reinterpret_cast<const __half2*>(&v[u]);
#pragma unroll
            for (int p = 0; p < 4; p++) {
                float2 f = __half22float2(h[p]);
                acc[p * 2 + 0] += w * f.x;
                acc[p * 2 + 1] += w * f.y;
            }
        }
    }
#pragma unroll
    for (int j = 0; j < 8; j++) part[ks][c16][j] = acc[j];
    __syncthreads();
    const int oc = tid >> 3, oj = tid & 7;
    float v = 0.f;
#pragma unroll
    for (int k = 0; k < 8; k++) v += part[k][oc][oj];
    out[b * 1024 + chunk * 128 + oc * 8 + oj] = v;
}

// =====================================================================
extern "C" void kernel_launch(void* const* d_in, const int* in_sizes, int n_in,
                              void* d_out, int out_size) {
    const float* input   = (const float*)d_in[0];
    const float* context = (const float*)d_in[1];
    const float* cov     = (const float*)d_in[2];
    const float* Wpre    = (const float*)d_in[3];
    const float* bpre    = (const float*)d_in[4];
    const float* Wq      = (const float*)d_in[5];
    const float* Wv      = (const float*)d_in[6];
    const float* Wcov    = (const float*)d_in[7];
    float* out = (float*)d_out;
    // layout: weightedContext (65536) | score (65536) | coverage_new (65536)
    //         | precompute (67108864)

    cudaFuncSetAttribute(k2_gemm, cudaFuncAttributeMaxDynamicSharedMemorySize, K2_SMEM);

    k0_cvt<<<4160, 256>>>((const float4*)context, (const float4*)Wpre);

    dim3 g1(8, 8);
    k1_target<<<g1, 256>>>(input, Wq);

    dim3 g2(8, 512);
    k2_gemm<<<g2, 256, K2_SMEM>>>(bpre, cov, Wv, Wcov, out + 196608);

    k3_softmax<<<64, 256>>>(cov, out);

    dim3 g4(64, 8);
    k4_wctx<<<g4, 128>>>(out + 65536, out);
}